// round 16
// baseline (speedup 1.0000x reference)
#include <cuda_runtime.h>
#include <math.h>
#include <stdint.h>

#define H    1024
#define NH   16
#define NKV  8
#define HD   128
#define II   3072
#define MAXS 16
#define LL   5
#define EPS  1e-6f
#define GRID 148
#define TPB  512
#define NWARP 16
#define NWG  (GRID * NWARP)                      // 2368 warps chip-wide
#define CACHE_F4 ((LL * NKV * MAXS * HD) / 4)    // 20480 float4 per cache

// Dynamic smem layout (floats): [0,3072) s_vec | [3072,35840) arena A | [35840,52224) arena B
#define SMEM_FLOATS (3072 + 32768 + 16384)
#define SMEM_BYTES  (SMEM_FLOATS * 4)

// Persistent state (allocation-free: __device__ globals)
__device__ float g_x[H];
__device__ float g_qraw[NH * HD];    // scaled by 1/inv (harmless: head-rms cancels)
__device__ float g_kraw[NKV * HD];   // scaled by 1/inv (harmless)
__device__ float g_vraw[NKV * HD];   // scaled by 1/inv (fixed in P2 by inv1)
__device__ float g_attn[NH * HD];
__device__ float g_gate[II];         // RAW gate GEMV results (silu deferred to P5)
__device__ float g_up[II];           // RAW up GEMV results
__device__ unsigned g_count;
__device__ unsigned g_release;

__device__ __forceinline__ float warp_sum(float v) {
#pragma unroll
    for (int o = 16; o; o >>= 1) v += __shfl_xor_sync(0xffffffffu, v, o);
    return v;
}

__device__ __forceinline__ float dot4(float4 a, float4 b) {
    return a.x * b.x + a.y * b.y + a.z * b.z + a.w * b.w;
}

__device__ __forceinline__ void cp16(float* smem_ptr, const float* gptr) {
    uint32_t s = (uint32_t)__cvta_generic_to_shared(smem_ptr);
    asm volatile("cp.async.cg.shared.global [%0], [%1], 16;" :: "r"(s), "l"(gptr));
}
#define CP_COMMIT() asm volatile("cp.async.commit_group;" ::: "memory")
#define CP_WAIT0()  asm volatile("cp.async.wait_group 0;" ::: "memory")
#define CP_WAIT1()  asm volatile("cp.async.wait_group 1;" ::: "memory")

// stage one 1024-float weight row into smem (8 x 16B per lane)
__device__ __forceinline__ void stage_row(float* dst, const float* src, int lane) {
#pragma unroll
    for (int j = 0; j < 8; j++)
        cp16(dst + (lane + 32 * j) * 4, src + (lane + 32 * j) * 4);
}

__global__ void reset_kernel() {
    g_count = 0;
    g_release = 0;
}

// Monotonic-epoch grid barrier (single atomic + single release flag).
__device__ __forceinline__ void grid_barrier(int& epoch) {
    __syncthreads();
    epoch++;
    if (threadIdx.x == 0) {
        __threadfence();
        unsigned a = atomicAdd(&g_count, 1u) + 1u;
        if (a == (unsigned)(GRID * epoch)) {
            atomicExch(&g_release, (unsigned)epoch);
        } else {
            while (((volatile unsigned*)&g_release)[0] < (unsigned)epoch) { }
        }
        __threadfence();
    }
    __syncthreads();
}

// Scale-free b-vector prep: s_vec = g_x ∘ w (no reduction, single sync).
__device__ __forceinline__ void block_prep(const float* __restrict__ w, float* h_s) {
    int tid = threadIdx.x;
    h_s[tid]       = g_x[tid] * w[tid];
    h_s[tid + 512] = g_x[tid + 512] * w[tid + 512];
    __syncthreads();
}

__device__ __forceinline__ const float* qkv_wrow(const float* wq_l, const float* wk_l,
                                                 const float* wv_l, int r) {
    if (r < 2048) return wq_l + (size_t)r * H;
    if (r < 3072) return wk_l + (size_t)(r - 2048) * H;
    return wv_l + (size_t)(r - 3072) * H;
}
__device__ __forceinline__ float* qkv_out(int r) {
    if (r < 2048) return g_qraw + r;
    if (r < 3072) return g_kraw + (r - 2048);
    return g_vraw + (r - 3072);
}

__global__ void __launch_bounds__(TPB, 1)
persistent_kernel(const float* __restrict__ hs,
                  const int* __restrict__ pos_p,
                  const float* __restrict__ pk,
                  const float* __restrict__ pv,
                  const float* __restrict__ wiln,
                  const float* __restrict__ wpaln,
                  const float* __restrict__ wq,
                  const float* __restrict__ wk,
                  const float* __restrict__ wv,
                  const float* __restrict__ wo,
                  const float* __restrict__ wqn,
                  const float* __restrict__ wkn,
                  const float* __restrict__ wg,
                  const float* __restrict__ wu,
                  const float* __restrict__ wd,
                  const float* __restrict__ wonorm,
                  float* __restrict__ out,
                  float* __restrict__ out_k,
                  float* __restrict__ out_v) {
    extern __shared__ float dyn[];
    float* s_vec = dyn;            // 3072 floats
    float* stA   = dyn + 3072;     // 32768 : qkv / gate-up stage (8KB/warp)
    float* stB   = dyn + 35840;    // 16384 : wo half-row stage (4KB/warp)

    __shared__ float red[NWARP];
    __shared__ float s_part[NWARP];
    __shared__ float p_s[MAXS];
    __shared__ float red2[8];
    __shared__ float s_inv1;       // rms inv for this layer's input x (used for v)
    __shared__ float s_inv2;       // rms inv for post-attn x' (used in P5 silu)

    int tid = threadIdx.x, bid = blockIdx.x;
    int lane = tid & 31, wid = tid >> 5;
    int epoch = 0;

    int r0 = wid * GRID + bid;            // [0,2368)
    int r1 = r0 + NWG;                    // qkv row b (<4096) / gu vrow b
    int r2 = r0 + 2 * NWG;                // gu vrow c (valid <6144)
    int prow = (wid >> 1) * GRID + bid;   // [0,1184) : o/down row (valid <1024)
    int half = wid & 1;
    bool hasR1 = (r1 < 4096);
    bool hasG  = (r2 < 2 * II);
    bool hasP  = (prow < H);

    float* myA0 = stA + wid * 2048;
    float* myA1 = stA + wid * 2048 + 1024;
    float* myB  = stB + wid * 1024;

    int pos = pos_p[0];

    // ---- prologue: residual init + cache copy + stage layer-0 qkv ----
    if (bid == 0) { g_x[tid] = hs[tid]; g_x[tid + 512] = hs[tid + 512]; }
    {
        int ci = bid * TPB + tid;
        if (ci < CACHE_F4) {
            ((float4*)out_k)[ci] = ((const float4*)pk)[ci];
            ((float4*)out_v)[ci] = ((const float4*)pv)[ci];
        }
    }
    stage_row(myA0, qkv_wrow(wq, wk, wv, r0), lane);
    if (hasR1) stage_row(myA1, qkv_wrow(wq, wk, wv, r1), lane);
    CP_COMMIT();                     // pending: [qkv]
    grid_barrier(epoch);

    for (int l = 0; l < LL; l++) {
        const float* wo_l = wo + (size_t)l * H * NH * HD;
        const float* wg_l = wg + (size_t)l * II * H;
        const float* wu_l = wu + (size_t)l * II * H;
        const float* wd_l = wd + (size_t)l * H * II;
        size_t lofs = (size_t)l * NKV * MAXS * HD;

        // ========== P1: issue wo stage; wait qkv; prep b (no norm); qkv GEMV ======
        if (hasP) stage_row(myB, wo_l + (size_t)prow * (NH * HD) + half * 1024, lane);
        CP_COMMIT();                 // pending: [qkv, wo]
        CP_WAIT1();                  // qkv done; pending: [wo]

        block_prep(wiln + l * H, s_vec);   // s_vec = x ∘ w_iln (unnormalized)
        {
            const float4* h4 = (const float4*)s_vec;
            const float4* w0 = (const float4*)myA0;
            const float4* w1 = (const float4*)myA1;
            float a0 = 0.f, a1 = 0.f;
#pragma unroll
            for (int j = 0; j < 8; j++) {
                float4 b = h4[lane + 32 * j];
                a0 += dot4(w0[lane + 32 * j], b);
                a1 += dot4(w1[lane + 32 * j], b);
            }
            a0 = warp_sum(a0);
            a1 = warp_sum(a1);
            if (lane == 0) {
                *qkv_out(r0) = a0;
                if (hasR1) *qkv_out(r1) = a1;
            }
        }
        grid_barrier(epoch);

        // ========== P2: issue gu stage; attention (16 blocks; computes inv1) ======
        stage_row(myA0, (r0 < II) ? (wg_l + (size_t)r0 * H) : (wu_l + (size_t)(r0 - II) * H), lane);
        stage_row(myA1, (r1 < II) ? (wg_l + (size_t)r1 * H) : (wu_l + (size_t)(r1 - II) * H), lane);
        CP_COMMIT();                 // pending: [wo, gu]

        if (bid < NH) {
            // inv1 = rsqrt(mean(x^2)+eps), computed locally (P2 has slack)
            {
                float x0 = g_x[tid], x1 = g_x[tid + 512];
                float ssq = warp_sum(x0 * x0 + x1 * x1);
                if (lane == 0) red[wid] = ssq;
                __syncthreads();
                if (wid == 0) {
                    float t = (lane < NWARP) ? red[lane] : 0.f;
                    t = warp_sum(t);
                    if (lane == 0) s_inv1 = rsqrtf(t * (1.f / H) + EPS);
                }
                __syncthreads();
            }
            float inv1 = s_inv1;

            int hq  = bid;
            int kvh = hq >> 1;
            bool act = tid < 128;
            float* k_s  = s_vec;
            float* q_s  = s_vec + 128;
            float* v_s  = s_vec + 256;
            float* tmpk = s_vec + 384;
            float* tmpq = s_vec + 512;

            float kv = 0.f, qv = 0.f, vv = 0.f;
            if (act) {
                kv = g_kraw[kvh * HD + tid];
                qv = g_qraw[hq * HD + tid];
                vv = inv1 * g_vraw[kvh * HD + tid];   // v needs the norm scalar
                float sk = warp_sum(kv * kv);
                float sq = warp_sum(qv * qv);
                if (lane == 0) { red2[wid] = sk; red2[4 + wid] = sq; }
            }
            __syncthreads();
            if (act) {
                float sumk = red2[0] + red2[1] + red2[2] + red2[3];
                float sumq = red2[4] + red2[5] + red2[6] + red2[7];
                float invk = rsqrtf(sumk * (1.f / HD) + EPS);
                float invq = rsqrtf(sumq * (1.f / HD) + EPS);
                tmpk[tid] = kv * invk * wkn[l * HD + tid];
                tmpq[tid] = qv * invq * wqn[l * HD + tid];
            }
            __syncthreads();
            if (act) {
                float kn = tmpk[tid], qn = tmpq[tid];
                float pk_ = tmpk[tid ^ 64];
                float pq_ = tmpq[tid ^ 64];
                const float NEG_LN_THETA_OVER_64 = -13.815510557964274f / 64.f;
                float f = (float)pos * expf((float)(tid & 63) * NEG_LN_THETA_OVER_64);
                float c = cosf(f), s = sinf(f);
                float sign = (tid < 64) ? -1.f : 1.f;
                float k_rope = kn * c + sign * pk_ * s;
                float q_rope = qn * c + sign * pq_ * s;
                k_s[tid] = k_rope;
                q_s[tid] = q_rope;
                v_s[tid] = vv;
                if ((hq & 1) == 0) {
                    out_k[lofs + (size_t)(kvh * MAXS + pos) * HD + tid] = k_rope;
                    out_v[lofs + (size_t)(kvh * MAXS + pos) * HD + tid] = vv;
                }
            }
            __syncthreads();

            const float scale = 0.08838834764831845f;  // 1/sqrt(128)
            if (act) {
                float q0 = q_s[lane], q1 = q_s[lane + 32], q2 = q_s[lane + 64], q3 = q_s[lane + 96];
                const float* kbase = pk + lofs + (size_t)kvh * MAXS * HD;
#pragma unroll
                for (int i = 0; i < 4; i++) {
                    int t = wid + 4 * i;
                    const float* kt = (t == pos) ? k_s : (kbase + (size_t)t * HD);
                    float d = q0 * kt[lane] + q1 * kt[lane + 32] + q2 * kt[lane + 64] + q3 * kt[lane + 96];
                    d = warp_sum(d);
                    if (lane == 0 && t <= pos) p_s[t] = d * scale;
                }
            }
            __syncthreads();
            if (tid < 32) {
                float v = (lane <= pos) ? p_s[lane] : -INFINITY;
                float m = v;
#pragma unroll
                for (int o = 16; o; o >>= 1) m = fmaxf(m, __shfl_xor_sync(0xffffffffu, m, o));
                float e = (lane <= pos) ? expf(v - m) : 0.f;
                float sum = warp_sum(e);
                if (lane < MAXS) p_s[lane] = e / sum;
            }
            __syncthreads();
            if (act) {
                const float* vbase = pv + lofs + (size_t)kvh * MAXS * HD;
                float acc = 0.f;
#pragma unroll
                for (int t = 0; t < MAXS; t++) {
                    float pt = (t <= pos) ? p_s[t] : 0.f;
                    float vt = (t == pos) ? v_s[tid] : vbase[(size_t)t * HD + tid];
                    acc += pt * vt;
                }
                g_attn[hq * HD + tid] = acc;
            }
        }
        grid_barrier(epoch);

        // ========== P3: wait wo; o-proj + residual; load G regs ==========
        CP_WAIT1();                  // wo done; pending: [gu]
        s_vec[tid]        = g_attn[tid];
        s_vec[tid + 512]  = g_attn[tid + 512];
        s_vec[tid + 1024] = g_attn[tid + 1024];
        s_vec[tid + 1536] = g_attn[tid + 1536];
        __syncthreads();
        if (hasP) {
            const float4* a4 = (const float4*)s_vec + half * 256;
            const float4* w4 = (const float4*)myB;
            float acc = 0.f;
#pragma unroll
            for (int j = 0; j < 8; j++) acc += dot4(w4[lane + 32 * j], a4[lane + 32 * j]);
            acc = warp_sum(acc);
            if (lane == 0) s_part[wid] = acc;
        }
        __syncthreads();
        if (hasP && half == 0 && lane == 0)
            g_x[prow] += s_part[wid] + s_part[wid + 1];

        float4 G[8];
        if (hasG) {
            const float4* p2 = (const float4*)(wu_l + (size_t)(r2 - II) * H);
#pragma unroll
            for (int j = 0; j < 8; j++) G[j] = p2[lane + 32 * j];
        }
        grid_barrier(epoch);

        // ========== P4: wait gu; prep b; gate/up RAW; stage qkv'; G; F; inv2 ======
        CP_WAIT0();                  // gate/up stage complete
        block_prep(wpaln + l * H, s_vec);   // s_vec = x' ∘ w_paln (unnormalized)
        {
            const float4* h4 = (const float4*)s_vec;
            const float4* w0 = (const float4*)myA0;
            const float4* w1 = (const float4*)myA1;
            float d0 = 0.f, d1 = 0.f;
#pragma unroll
            for (int j = 0; j < 8; j++) {
                float4 b = h4[lane + 32 * j];
                d0 += dot4(w0[lane + 32 * j], b);
                d1 += dot4(w1[lane + 32 * j], b);
            }
            d0 = warp_sum(d0);
            d1 = warp_sum(d1);
            if (lane == 0) {
                g_gate[r0] = d0;                     // RAW (silu in P5 with inv2)
                if (r1 < II) g_gate[r1] = d1;
                else         g_up[r1 - II] = d1;
            }
        }

        // stage next layer's qkv into A
        if (l + 1 < LL) {
            const float* wq_n = wq + (size_t)(l + 1) * NH * HD * H;
            const float* wk_n = wk + (size_t)(l + 1) * NKV * HD * H;
            const float* wv_n = wv + (size_t)(l + 1) * NKV * HD * H;
            stage_row(myA0, qkv_wrow(wq_n, wk_n, wv_n, r0), lane);
            if (hasR1) stage_row(myA1, qkv_wrow(wq_n, wk_n, wv_n, r1), lane);
        }
        CP_COMMIT();                 // pending: [qkv']

        if (hasG) {
            const float4* h4 = (const float4*)s_vec;
            float d2 = 0.f;
#pragma unroll
            for (int j = 0; j < 8; j++) d2 += dot4(G[j], h4[lane + 32 * j]);
            d2 = warp_sum(d2);
            if (lane == 0) g_up[r2 - II] = d2;
        }

        float4 F[12];
        if (hasP) {
            const float4* w4 = (const float4*)(wd_l + (size_t)prow * II) + half * 384;
#pragma unroll
            for (int j = 0; j < 12; j++) F[j] = w4[lane + 32 * j];
        }

        // inv2 for x' (x' is L1-hot from block_prep above); off the GEMV path
        {
            float x0 = g_x[tid], x1 = g_x[tid + 512];
            float ssq = warp_sum(x0 * x0 + x1 * x1);
            if (lane == 0) red[wid] = ssq;
            __syncthreads();
            if (wid == 0) {
                float t = (lane < NWARP) ? red[lane] : 0.f;
                t = warp_sum(t);
                if (lane == 0) s_inv2 = rsqrtf(t * (1.f / H) + EPS);
            }
        }
        grid_barrier(epoch);

        // ========== P5: combine t (silu with inv2); down + residual ==========
        {
            float inv2 = s_inv2;
#pragma unroll
            for (int i = 0; i < 6; i++) {
                int idx = tid + 512 * i;
                float gg = inv2 * g_gate[idx];
                float uu = inv2 * g_up[idx];
                s_vec[idx] = (gg / (1.f + expf(-gg))) * uu;
            }
        }
        __syncthreads();
        if (hasP) {
            const float4* t4 = (const float4*)s_vec + half * 384;
            float acc = 0.f;
#pragma unroll
            for (int j = 0; j < 12; j++) acc += dot4(F[j], t4[lane + 32 * j]);
            acc = warp_sum(acc);
            if (lane == 0) s_part[wid] = acc;
        }
        __syncthreads();
        if (hasP && half == 0 && lane == 0)
            g_x[prow] += s_part[wid] + s_part[wid + 1];
        grid_barrier(epoch);
    }

    // ---- final: out = rms(x, w_onorm), block 0 ----
    if (bid == 0) {
        float x0 = g_x[tid], x1 = g_x[tid + 512];
        float ssq = warp_sum(x0 * x0 + x1 * x1);
        if (lane == 0) red[wid] = ssq;
        __syncthreads();
        if (wid == 0) {
            float t = (lane < NWARP) ? red[lane] : 0.f;
            t = warp_sum(t);
            if (lane == 0) red[0] = rsqrtf(t * (1.f / H) + EPS);
        }
        __syncthreads();
        float inv = red[0];
        out[tid]       = x0 * inv * wonorm[tid];
        out[tid + 512] = x1 * inv * wonorm[tid + 512];
    }
}

extern "C" void kernel_launch(void* const* d_in, const int* in_sizes, int n_in,
                              void* d_out, int out_size) {
    const float* hs     = (const float*)d_in[0];
    const int*   pos    = (const int*)d_in[1];
    const float* pk     = (const float*)d_in[2];
    const float* pv     = (const float*)d_in[3];
    const float* wiln   = (const float*)d_in[4];
    const float* wpaln  = (const float*)d_in[5];
    const float* wq     = (const float*)d_in[6];
    const float* wk     = (const float*)d_in[7];
    const float* wv     = (const float*)d_in[8];
    const float* wo     = (const float*)d_in[9];
    const float* wqn    = (const float*)d_in[10];
    const float* wkn    = (const float*)d_in[11];
    const float* wg     = (const float*)d_in[12];
    const float* wu     = (const float*)d_in[13];
    const float* wd     = (const float*)d_in[14];
    const float* wonorm = (const float*)d_in[15];

    float* out   = (float*)d_out;
    float* out_k = out + H;
    float* out_v = out_k + (size_t)LL * NKV * MAXS * HD;

    cudaFuncSetAttribute(persistent_kernel,
                         cudaFuncAttributeMaxDynamicSharedMemorySize, SMEM_BYTES);

    reset_kernel<<<1, 1>>>();
    persistent_kernel<<<GRID, TPB, SMEM_BYTES>>>(hs, pos, pk, pv, wiln, wpaln,
                                                 wq, wk, wv, wo, wqn, wkn,
                                                 wg, wu, wd, wonorm,
                                                 out, out_k, out_v);
}

// round 17
// speedup vs baseline: 1.0680x; 1.0680x over previous
#include <cuda_runtime.h>
#include <math.h>
#include <stdint.h>

#define H    1024
#define NH   16
#define NKV  8
#define HD   128
#define II   3072
#define MAXS 16
#define LL   5
#define EPS  1e-6f
#define GRID 148
#define TPB  512
#define NWARP 16
#define NWG  (GRID * NWARP)                      // 2368 warps chip-wide
#define CACHE_F4 ((LL * NKV * MAXS * HD) / 4)    // 20480 float4 per cache

// Dynamic smem layout (floats): [0,3072) s_vec | [3072,35840) arena A | [35840,52224) arena B
#define SMEM_FLOATS (3072 + 32768 + 16384)
#define SMEM_BYTES  (SMEM_FLOATS * 4)

// Persistent state (allocation-free: __device__ globals; zero-init at load,
// self-reset in kernel epilogue so graph replays are deterministic)
__device__ float g_x[H];
__device__ float g_qraw[NH * HD];    // scaled by 1/inv1 (head-rms cancels it)
__device__ float g_kraw[NKV * HD];   // scaled by 1/inv1 (head-rms cancels it)
__device__ float g_vraw[NKV * HD];   // scaled by 1/inv1 (fixed in P2 with inv1)
__device__ float g_attn[NH * HD];
__device__ float g_gate[II];
__device__ float g_up[II];
__device__ float g_inv1;             // rms inv of layer-input x (written by block 0 in P1)
__device__ unsigned g_count;
__device__ unsigned g_release;
__device__ unsigned g_count2;

__device__ __forceinline__ float warp_sum(float v) {
#pragma unroll
    for (int o = 16; o; o >>= 1) v += __shfl_xor_sync(0xffffffffu, v, o);
    return v;
}

__device__ __forceinline__ float dot4(float4 a, float4 b) {
    return a.x * b.x + a.y * b.y + a.z * b.z + a.w * b.w;
}

__device__ __forceinline__ void cp16(float* smem_ptr, const float* gptr) {
    uint32_t s = (uint32_t)__cvta_generic_to_shared(smem_ptr);
    asm volatile("cp.async.cg.shared.global [%0], [%1], 16;" :: "r"(s), "l"(gptr));
}
#define CP_COMMIT() asm volatile("cp.async.commit_group;" ::: "memory")
#define CP_WAIT0()  asm volatile("cp.async.wait_group 0;" ::: "memory")
#define CP_WAIT1()  asm volatile("cp.async.wait_group 1;" ::: "memory")

// stage one 1024-float weight row into smem (8 x 16B per lane)
__device__ __forceinline__ void stage_row(float* dst, const float* src, int lane) {
#pragma unroll
    for (int j = 0; j < 8; j++)
        cp16(dst + (lane + 32 * j) * 4, src + (lane + 32 * j) * 4);
}

// Monotonic-epoch grid barrier (single atomic + single release flag).
// Grid fully co-resident (148 blocks, 1/SM).
__device__ __forceinline__ void grid_barrier(int& epoch) {
    __syncthreads();
    epoch++;
    if (threadIdx.x == 0) {
        __threadfence();
        unsigned a = atomicAdd(&g_count, 1u) + 1u;
        if (a == (unsigned)(GRID * epoch)) {
            atomicExch(&g_release, (unsigned)epoch);
        } else {
            while (((volatile unsigned*)&g_release)[0] < (unsigned)epoch) { }
        }
        __threadfence();
    }
    __syncthreads();
}

// Scale-free b-vector prep: s_vec = g_x ∘ w (no reduction, single sync).
__device__ __forceinline__ void block_prep(const float* __restrict__ w, float* h_s) {
    int tid = threadIdx.x;
    h_s[tid]       = g_x[tid] * w[tid];
    h_s[tid + 512] = g_x[tid + 512] * w[tid + 512];
    __syncthreads();
}

// Full RMSNorm prep (used in P4 where the scale cannot be deferred cheaply).
__device__ __forceinline__ void block_norm(const float* __restrict__ w,
                                           float* h_s, float* red) {
    int tid = threadIdx.x, lane = tid & 31, wid = tid >> 5;
    float x0 = g_x[tid], x1 = g_x[tid + 512];
    float ssq = warp_sum(x0 * x0 + x1 * x1);
    if (lane == 0) red[wid] = ssq;
    __syncthreads();
    if (wid == 0) {
        float t = (lane < NWARP) ? red[lane] : 0.f;
        t = warp_sum(t);
        if (lane == 0) red[0] = rsqrtf(t * (1.f / H) + EPS);
    }
    __syncthreads();
    float inv = red[0];
    h_s[tid]       = x0 * inv * w[tid];
    h_s[tid + 512] = x1 * inv * w[tid + 512];
    __syncthreads();
}

__device__ __forceinline__ const float* qkv_wrow(const float* wq_l, const float* wk_l,
                                                 const float* wv_l, int r) {
    if (r < 2048) return wq_l + (size_t)r * H;
    if (r < 3072) return wk_l + (size_t)(r - 2048) * H;
    return wv_l + (size_t)(r - 3072) * H;
}
__device__ __forceinline__ float* qkv_out(int r) {
    if (r < 2048) return g_qraw + r;
    if (r < 3072) return g_kraw + (r - 2048);
    return g_vraw + (r - 3072);
}

__global__ void __launch_bounds__(TPB, 1)
persistent_kernel(const float* __restrict__ hs,
                  const int* __restrict__ pos_p,
                  const float* __restrict__ pk,
                  const float* __restrict__ pv,
                  const float* __restrict__ wiln,
                  const float* __restrict__ wpaln,
                  const float* __restrict__ wq,
                  const float* __restrict__ wk,
                  const float* __restrict__ wv,
                  const float* __restrict__ wo,
                  const float* __restrict__ wqn,
                  const float* __restrict__ wkn,
                  const float* __restrict__ wg,
                  const float* __restrict__ wu,
                  const float* __restrict__ wd,
                  const float* __restrict__ wonorm,
                  float* __restrict__ out,
                  float* __restrict__ out_k,
                  float* __restrict__ out_v) {
    extern __shared__ float dyn[];
    float* s_vec = dyn;            // 3072 floats
    float* stA   = dyn + 3072;     // 32768 : qkv / gate-up stage (8KB/warp)
    float* stB   = dyn + 35840;    // 16384 : wo half-row stage (4KB/warp)

    __shared__ float red[NWARP];
    __shared__ float s_part[NWARP];
    __shared__ float p_s[MAXS];
    __shared__ float red2[8];
    __shared__ float s_inv1;

    int tid = threadIdx.x, bid = blockIdx.x;
    int lane = tid & 31, wid = tid >> 5;
    int epoch = 0;

    int r0 = wid * GRID + bid;            // [0,2368)
    int r1 = r0 + NWG;                    // qkv row b (<4096) / gu vrow b
    int r2 = r0 + 2 * NWG;                // gu vrow c (valid <6144)
    int prow = (wid >> 1) * GRID + bid;   // [0,1184) : o/down row (valid <1024)
    int half = wid & 1;
    bool hasR1 = (r1 < 4096);
    bool hasG  = (r2 < 2 * II);
    bool hasP  = (prow < H);

    float* myA0 = stA + wid * 2048;
    float* myA1 = stA + wid * 2048 + 1024;
    float* myB  = stB + wid * 1024;

    int pos = pos_p[0];

    // ---- prologue: residual init + cache copy + stage layer-0 qkv ----
    if (bid == 0) { g_x[tid] = hs[tid]; g_x[tid + 512] = hs[tid + 512]; }
    {
        int ci = bid * TPB + tid;
        if (ci < CACHE_F4) {
            ((float4*)out_k)[ci] = ((const float4*)pk)[ci];
            ((float4*)out_v)[ci] = ((const float4*)pv)[ci];
        }
    }
    stage_row(myA0, qkv_wrow(wq, wk, wv, r0), lane);
    if (hasR1) stage_row(myA1, qkv_wrow(wq, wk, wv, r1), lane);
    CP_COMMIT();                     // pending: [qkv]
    grid_barrier(epoch);

    for (int l = 0; l < LL; l++) {
        const float* wo_l = wo + (size_t)l * H * NH * HD;
        const float* wg_l = wg + (size_t)l * II * H;
        const float* wu_l = wu + (size_t)l * II * H;
        const float* wd_l = wd + (size_t)l * H * II;
        size_t lofs = (size_t)l * NKV * MAXS * HD;

        // ========== P1: issue wo stage; wait qkv; prep b; qkv GEMV (scale-free) ====
        if (hasP) stage_row(myB, wo_l + (size_t)prow * (NH * HD) + half * 1024, lane);
        CP_COMMIT();                 // pending: [qkv, wo]
        CP_WAIT1();                  // qkv done; pending: [wo]

        block_prep(wiln + l * H, s_vec);    // s_vec = x ∘ w_iln (unnormalized)
        {
            const float4* h4 = (const float4*)s_vec;
            const float4* w0 = (const float4*)myA0;
            const float4* w1 = (const float4*)myA1;
            float a0 = 0.f, a1 = 0.f;
#pragma unroll
            for (int j = 0; j < 8; j++) {
                float4 b = h4[lane + 32 * j];
                a0 += dot4(w0[lane + 32 * j], b);
                a1 += dot4(w1[lane + 32 * j], b);
            }
            a0 = warp_sum(a0);
            a1 = warp_sum(a1);
            if (lane == 0) {
                *qkv_out(r0) = a0;
                if (hasR1) *qkv_out(r1) = a1;
            }
        }

        // attention blocks compute inv1 now (hidden in barrier-arrival skew)
        if (bid < NH) {
            float x0 = g_x[tid], x1 = g_x[tid + 512];
            float ssq = warp_sum(x0 * x0 + x1 * x1);
            if (lane == 0) red[wid] = ssq;
            __syncthreads();
            if (wid == 0) {
                float t = (lane < NWARP) ? red[lane] : 0.f;
                t = warp_sum(t);
                if (lane == 0) s_inv1 = rsqrtf(t * (1.f / H) + EPS);
            }
        }
        grid_barrier(epoch);

        // ========== P2: issue gu stage (fills attn window); attention (16 blocks) ==
        stage_row(myA0, (r0 < II) ? (wg_l + (size_t)r0 * H) : (wu_l + (size_t)(r0 - II) * H), lane);
        stage_row(myA1, (r1 < II) ? (wg_l + (size_t)r1 * H) : (wu_l + (size_t)(r1 - II) * H), lane);
        CP_COMMIT();                 // pending: [wo, gu]

        if (bid < NH) {
            float inv1 = s_inv1;
            int hq  = bid;
            int kvh = hq >> 1;
            bool act = tid < 128;
            float* k_s  = s_vec;
            float* q_s  = s_vec + 128;
            float* v_s  = s_vec + 256;
            float* tmpk = s_vec + 384;
            float* tmpq = s_vec + 512;

            float kv = 0.f, qv = 0.f, vv = 0.f;
            if (act) {
                kv = g_kraw[kvh * HD + tid];
                qv = g_qraw[hq * HD + tid];
                vv = inv1 * g_vraw[kvh * HD + tid];   // v needs the norm scalar
                float sk = warp_sum(kv * kv);
                float sq = warp_sum(qv * qv);
                if (lane == 0) { red2[wid] = sk; red2[4 + wid] = sq; }
            }
            __syncthreads();
            if (act) {
                float sumk = red2[0] + red2[1] + red2[2] + red2[3];
                float sumq = red2[4] + red2[5] + red2[6] + red2[7];
                float invk = rsqrtf(sumk * (1.f / HD) + EPS);
                float invq = rsqrtf(sumq * (1.f / HD) + EPS);
                tmpk[tid] = kv * invk * wkn[l * HD + tid];
                tmpq[tid] = qv * invq * wqn[l * HD + tid];
            }
            __syncthreads();
            if (act) {
                float kn = tmpk[tid], qn = tmpq[tid];
                float pk_ = tmpk[tid ^ 64];
                float pq_ = tmpq[tid ^ 64];
                const float NEG_LN_THETA_OVER_64 = -13.815510557964274f / 64.f;
                float f = (float)pos * expf((float)(tid & 63) * NEG_LN_THETA_OVER_64);
                float c = cosf(f), s = sinf(f);
                float sign = (tid < 64) ? -1.f : 1.f;
                float k_rope = kn * c + sign * pk_ * s;
                float q_rope = qn * c + sign * pq_ * s;
                k_s[tid] = k_rope;
                q_s[tid] = q_rope;
                v_s[tid] = vv;
                if ((hq & 1) == 0) {
                    out_k[lofs + (size_t)(kvh * MAXS + pos) * HD + tid] = k_rope;
                    out_v[lofs + (size_t)(kvh * MAXS + pos) * HD + tid] = vv;
                }
            }
            __syncthreads();

            const float scale = 0.08838834764831845f;  // 1/sqrt(128)
            if (act) {
                float q0 = q_s[lane], q1 = q_s[lane + 32], q2 = q_s[lane + 64], q3 = q_s[lane + 96];
                const float* kbase = pk + lofs + (size_t)kvh * MAXS * HD;
#pragma unroll
                for (int i = 0; i < 4; i++) {
                    int t = wid + 4 * i;
                    const float* kt = (t == pos) ? k_s : (kbase + (size_t)t * HD);
                    float d = q0 * kt[lane] + q1 * kt[lane + 32] + q2 * kt[lane + 64] + q3 * kt[lane + 96];
                    d = warp_sum(d);
                    if (lane == 0 && t <= pos) p_s[t] = d * scale;
                }
            }
            __syncthreads();
            if (tid < 32) {
                float v = (lane <= pos) ? p_s[lane] : -INFINITY;
                float m = v;
#pragma unroll
                for (int o = 16; o; o >>= 1) m = fmaxf(m, __shfl_xor_sync(0xffffffffu, m, o));
                float e = (lane <= pos) ? expf(v - m) : 0.f;
                float sum = warp_sum(e);
                if (lane < MAXS) p_s[lane] = e / sum;
            }
            __syncthreads();
            if (act) {
                const float* vbase = pv + lofs + (size_t)kvh * MAXS * HD;
                float acc = 0.f;
#pragma unroll
                for (int t = 0; t < MAXS; t++) {
                    float pt = (t <= pos) ? p_s[t] : 0.f;
                    float vt = (t == pos) ? v_s[tid] : vbase[(size_t)t * HD + tid];
                    acc += pt * vt;
                }
                g_attn[hq * HD + tid] = acc;
            }
        }
        grid_barrier(epoch);

        // ========== P3: hoist attn loads; wait wo; o-proj + residual; load G ======
        float t0 = g_attn[tid];
        float t1 = g_attn[tid + 512];
        float t2 = g_attn[tid + 1024];
        float t3 = g_attn[tid + 1536];
        CP_WAIT1();                  // wo done; pending: [gu]
        s_vec[tid]        = t0;
        s_vec[tid + 512]  = t1;
        s_vec[tid + 1024] = t2;
        s_vec[tid + 1536] = t3;
        __syncthreads();
        if (hasP) {
            const float4* a4 = (const float4*)s_vec + half * 256;
            const float4* w4 = (const float4*)myB;
            float acc = 0.f;
#pragma unroll
            for (int j = 0; j < 8; j++) acc += dot4(w4[lane + 32 * j], a4[lane + 32 * j]);
            acc = warp_sum(acc);
            if (lane == 0) s_part[wid] = acc;
        }
        __syncthreads();
        if (hasP && half == 0 && lane == 0)
            g_x[prow] += s_part[wid] + s_part[wid + 1];

        float4 G[8];
        if (hasG) {
            const float4* p2 = (const float4*)(wu_l + (size_t)(r2 - II) * H);
#pragma unroll
            for (int j = 0; j < 8; j++) G[j] = p2[lane + 32 * j];
        }
        grid_barrier(epoch);

        // ========== P4: wait gu; norm; gate/up; stage qkv'; consume G; load F ======
        CP_WAIT0();                  // gate/up stage complete
        block_norm(wpaln + l * H, s_vec, red);
        {
            const float4* h4 = (const float4*)s_vec;
            const float4* w0 = (const float4*)myA0;
            const float4* w1 = (const float4*)myA1;
            float d0 = 0.f, d1 = 0.f;
#pragma unroll
            for (int j = 0; j < 8; j++) {
                float4 b = h4[lane + 32 * j];
                d0 += dot4(w0[lane + 32 * j], b);
                d1 += dot4(w1[lane + 32 * j], b);
            }
            d0 = warp_sum(d0);
            d1 = warp_sum(d1);
            if (lane == 0) {
                g_gate[r0] = d0 / (1.f + expf(-d0));     // r0 always gate
                if (r1 < II) g_gate[r1] = d1 / (1.f + expf(-d1));
                else         g_up[r1 - II] = d1;
            }
        }

        // stage next layer's qkv into A (slots consumed by gate/up above)
        if (l + 1 < LL) {
            const float* wq_n = wq + (size_t)(l + 1) * NH * HD * H;
            const float* wk_n = wk + (size_t)(l + 1) * NKV * HD * H;
            const float* wv_n = wv + (size_t)(l + 1) * NKV * HD * H;
            stage_row(myA0, qkv_wrow(wq_n, wk_n, wv_n, r0), lane);
            if (hasR1) stage_row(myA1, qkv_wrow(wq_n, wk_n, wv_n, r1), lane);
        }
        CP_COMMIT();                 // pending: [qkv']

        if (hasG) {
            const float4* h4 = (const float4*)s_vec;
            float d2 = 0.f;
#pragma unroll
            for (int j = 0; j < 8; j++) d2 += dot4(G[j], h4[lane + 32 * j]);
            d2 = warp_sum(d2);
            if (lane == 0) g_up[r2 - II] = d2;
        }

        float4 F[12];
        if (hasP) {
            const float4* w4 = (const float4*)(wd_l + (size_t)prow * II) + half * 384;
#pragma unroll
            for (int j = 0; j < 12; j++) F[j] = w4[lane + 32 * j];
        }
        grid_barrier(epoch);

        // ========== P5: combine t; down + residual (F loaded at P4-mid) ==========
#pragma unroll
        for (int i = 0; i < 6; i++) {
            int idx = tid + 512 * i;
            s_vec[idx] = g_gate[idx] * g_up[idx];
        }
        __syncthreads();
        if (hasP) {
            const float4* t4 = (const float4*)s_vec + half * 384;
            float acc = 0.f;
#pragma unroll
            for (int j = 0; j < 12; j++) acc += dot4(F[j], t4[lane + 32 * j]);
            acc = warp_sum(acc);
            if (lane == 0) s_part[wid] = acc;
        }
        __syncthreads();
        if (hasP && half == 0 && lane == 0)
            g_x[prow] += s_part[wid] + s_part[wid + 1];
        grid_barrier(epoch);
    }

    // ---- final: out = rms(x, w_onorm), block 0 ----
    if (bid == 0) {
        float x0 = g_x[tid], x1 = g_x[tid + 512];
        float ssq = warp_sum(x0 * x0 + x1 * x1);
        if (lane == 0) red[wid] = ssq;
        __syncthreads();
        if (wid == 0) {
            float t = (lane < NWARP) ? red[lane] : 0.f;
            t = warp_sum(t);
            if (lane == 0) red[0] = rsqrtf(t * (1.f / H) + EPS);
        }
        __syncthreads();
        float inv = red[0];
        out[tid]       = x0 * inv * wonorm[tid];
        out[tid + 512] = x1 * inv * wonorm[tid + 512];
    }

    // ---- epilogue: self-reset barrier counters (replaces reset_kernel node).
    // Every block arrives here only after passing its final grid_barrier wait,
    // so once all GRID blocks have incremented g_count2, no thread can still
    // be polling g_release — the last arriver resets all counters safely.
    __syncthreads();
    if (tid == 0) {
        __threadfence();
        unsigned a = atomicAdd(&g_count2, 1u);
        if (a == (unsigned)(GRID - 1)) {
            g_count = 0u;
            g_release = 0u;
            g_count2 = 0u;
            __threadfence();
        }
    }
}

extern "C" void kernel_launch(void* const* d_in, const int* in_sizes, int n_in,
                              void* d_out, int out_size) {
    const float* hs     = (const float*)d_in[0];
    const int*   pos    = (const int*)d_in[1];
    const float* pk     = (const float*)d_in[2];
    const float* pv     = (const float*)d_in[3];
    const float* wiln   = (const float*)d_in[4];
    const float* wpaln  = (const float*)d_in[5];
    const float* wq     = (const float*)d_in[6];
    const float* wk     = (const float*)d_in[7];
    const float* wv     = (const float*)d_in[8];
    const float* wo     = (const float*)d_in[9];
    const float* wqn    = (const float*)d_in[10];
    const float* wkn    = (const float*)d_in[11];
    const float* wg     = (const float*)d_in[12];
    const float* wu     = (const float*)d_in[13];
    const float* wd     = (const float*)d_in[14];
    const float* wonorm = (const float*)d_in[15];

    float* out   = (float*)d_out;
    float* out_k = out + H;
    float* out_v = out_k + (size_t)LL * NKV * MAXS * HD;

    cudaFuncSetAttribute(persistent_kernel,
                         cudaFuncAttributeMaxDynamicSharedMemorySize, SMEM_BYTES);

    persistent_kernel<<<GRID, TPB, SMEM_BYTES>>>(hs, pos, pk, pv, wiln, wpaln,
                                                 wq, wk, wv, wo, wqn, wkn,
                                                 wg, wu, wd, wonorm,
                                                 out, out_k, out_v);
}